// round 1
// baseline (speedup 1.0000x reference)
#include <cuda_runtime.h>
#include <math.h>

// ---------------------------------------------------------------------------
// Problem: out = softmax((xWq+bq)(xWk+bk)^T / sqrt(H)) (xWv+bv)
// B=4, S=2048, D=H=1024. fp32 throughout (round-0 correctness-safe baseline).
// ---------------------------------------------------------------------------

#define BATCH 4
#define SEQ   2048
#define DIM   1024

// Scratch (no allocations allowed -> __device__ globals)
__device__ float g_Q[BATCH * SEQ * DIM];
__device__ float g_K[BATCH * SEQ * DIM];
__device__ float g_V[BATCH * SEQ * DIM];
__device__ float g_S[BATCH * SEQ * SEQ];

// ---------------------------------------------------------------------------
// Tiled fp32 GEMM: C[M,N] = alpha * A[M,K] * op(B) (+ bias[n])
//   TRANSB=false: B is [K,N] row-major (ldb = N)
//   TRANSB=true : B is [N,K] row-major (ldb = K), i.e. C = A * B^T
// A row stride = K, C row stride = N (holds for every call site here).
// All of M,N,K are multiples of 64/16 -> no bounds checks.
// 64x64 block, BK=16, 256 threads, 4x4 micro-tile per thread.
// ---------------------------------------------------------------------------
#define BM 64
#define BN 64
#define BK 16
#define PAD 68   // row pitch (floats): multiple of 4 (aligned float4) and != 64 (banks)

template <bool TRANSB, bool BIAS>
__global__ __launch_bounds__(256)
void gemm64(const float* __restrict__ A, const float* __restrict__ B,
            const float* __restrict__ bias, float* __restrict__ C,
            int M, int N, int K,
            long long sA, long long sB, long long sC, float alpha)
{
    A += (long long)blockIdx.z * sA;
    B += (long long)blockIdx.z * sB;
    C += (long long)blockIdx.z * sC;

    __shared__ float As[BK][PAD];   // As[k][m]
    __shared__ float Bs[BK][PAD];   // Bs[k][n]

    const int t  = threadIdx.x;
    const int tx = t & 15;          // n direction
    const int ty = t >> 4;          // m direction
    const int m0 = blockIdx.y * BM;
    const int n0 = blockIdx.x * BN;

    // A tile load mapping: 64 rows x 16 k, one float4 per thread
    const int ar = t >> 2;           // 0..63 (m within tile)
    const int ac = (t & 3) * 4;      // 0..12 (k seg)
    // B tile load mapping
    const int br_t = t >> 2;         // TRANSB: n within tile
    const int bc_t = (t & 3) * 4;    //         k seg
    const int br_n = t >> 4;         // !TRANSB: k within tile (0..15)
    const int bc_n = (t & 15) * 4;   //          n seg

    float acc[4][4] = {};

    for (int k0 = 0; k0 < K; k0 += BK) {
        // load A (transpose into As[k][m])
        float4 a = *reinterpret_cast<const float4*>(
            A + (long long)(m0 + ar) * K + (k0 + ac));
        As[ac + 0][ar] = a.x;
        As[ac + 1][ar] = a.y;
        As[ac + 2][ar] = a.z;
        As[ac + 3][ar] = a.w;

        if (TRANSB) {
            float4 b = *reinterpret_cast<const float4*>(
                B + (long long)(n0 + br_t) * K + (k0 + bc_t));
            Bs[bc_t + 0][br_t] = b.x;
            Bs[bc_t + 1][br_t] = b.y;
            Bs[bc_t + 2][br_t] = b.z;
            Bs[bc_t + 3][br_t] = b.w;
        } else {
            float4 b = *reinterpret_cast<const float4*>(
                B + (long long)(k0 + br_n) * N + (n0 + bc_n));
            *reinterpret_cast<float4*>(&Bs[br_n][bc_n]) = b;
        }
        __syncthreads();

#pragma unroll
        for (int kk = 0; kk < BK; kk++) {
            float4 av = *reinterpret_cast<const float4*>(&As[kk][ty * 4]);
            float4 bv = *reinterpret_cast<const float4*>(&Bs[kk][tx * 4]);
            float ra[4] = {av.x, av.y, av.z, av.w};
            float rb[4] = {bv.x, bv.y, bv.z, bv.w};
#pragma unroll
            for (int i = 0; i < 4; i++)
#pragma unroll
                for (int j = 0; j < 4; j++)
                    acc[i][j] += ra[i] * rb[j];
        }
        __syncthreads();
    }

    // epilogue
    float4 bz = make_float4(0.f, 0.f, 0.f, 0.f);
    if (BIAS)
        bz = *reinterpret_cast<const float4*>(bias + n0 + tx * 4);
#pragma unroll
    for (int i = 0; i < 4; i++) {
        long long m = m0 + ty * 4 + i;
        float4 o;
        o.x = acc[i][0] * alpha + bz.x;
        o.y = acc[i][1] * alpha + bz.y;
        o.z = acc[i][2] * alpha + bz.z;
        o.w = acc[i][3] * alpha + bz.w;
        *reinterpret_cast<float4*>(C + m * N + n0 + tx * 4) = o;
    }
}

// ---------------------------------------------------------------------------
// Row softmax over rows of length SEQ (2048). One CTA (256 thr) per row,
// 8 elements per thread held in registers.
// ---------------------------------------------------------------------------
__global__ __launch_bounds__(256)
void softmax_rows(float* __restrict__ S)
{
    float* row = S + (long long)blockIdx.x * SEQ;
    __shared__ float red[256];
    const int t = threadIdx.x;

    float v[8];
    float mx = -INFINITY;
#pragma unroll
    for (int i = 0; i < 8; i++) {
        v[i] = row[t + i * 256];
        mx = fmaxf(mx, v[i]);
    }
    red[t] = mx;
    __syncthreads();
#pragma unroll
    for (int s = 128; s > 0; s >>= 1) {
        if (t < s) red[t] = fmaxf(red[t], red[t + s]);
        __syncthreads();
    }
    mx = red[0];
    __syncthreads();

    float sum = 0.f;
#pragma unroll
    for (int i = 0; i < 8; i++) {
        v[i] = __expf(v[i] - mx);
        sum += v[i];
    }
    red[t] = sum;
    __syncthreads();
#pragma unroll
    for (int s = 128; s > 0; s >>= 1) {
        if (t < s) red[t] += red[t + s];
        __syncthreads();
    }
    float inv = 1.0f / red[0];
#pragma unroll
    for (int i = 0; i < 8; i++)
        row[t + i * 256] = v[i] * inv;
}

// ---------------------------------------------------------------------------
// Launch
// inputs (metadata order): x, Wq, bq, Wk, bk, Wv, bv
// ---------------------------------------------------------------------------
extern "C" void kernel_launch(void* const* d_in, const int* in_sizes, int n_in,
                              void* d_out, int out_size)
{
    const float* x  = (const float*)d_in[0];
    const float* Wq = (const float*)d_in[1];
    const float* bq = (const float*)d_in[2];
    const float* Wk = (const float*)d_in[3];
    const float* bk = (const float*)d_in[4];
    const float* Wv = (const float*)d_in[5];
    const float* bv = (const float*)d_in[6];
    float* out = (float*)d_out;

    static float *pQ = nullptr, *pK = nullptr, *pV = nullptr, *pS = nullptr;
    if (!pQ) {
        cudaGetSymbolAddress((void**)&pQ, g_Q);
        cudaGetSymbolAddress((void**)&pK, g_K);
        cudaGetSymbolAddress((void**)&pV, g_V);
        cudaGetSymbolAddress((void**)&pS, g_S);
    }

    const int M = BATCH * SEQ;          // 8192
    const float scale = 0.03125f;       // 1/sqrt(1024)

    // 1) QKV projections: [8192,1024] x [1024,1024] + bias
    dim3 gQKV(DIM / BN, M / BM, 1);
    gemm64<false, true><<<gQKV, 256>>>(x, Wq, bq, pQ, M, DIM, DIM, 0, 0, 0, 1.0f);
    gemm64<false, true><<<gQKV, 256>>>(x, Wk, bk, pK, M, DIM, DIM, 0, 0, 0, 1.0f);
    gemm64<false, true><<<gQKV, 256>>>(x, Wv, bv, pV, M, DIM, DIM, 0, 0, 0, 1.0f);

    // 2) scores = Q K^T * scale   (per batch, NT)
    dim3 gS(SEQ / BN, SEQ / BM, BATCH);
    gemm64<true, false><<<gS, 256>>>(pQ, pK, nullptr, pS,
                                     SEQ, SEQ, DIM,
                                     (long long)SEQ * DIM, (long long)SEQ * DIM,
                                     (long long)SEQ * SEQ, scale);

    // 3) softmax rows
    softmax_rows<<<BATCH * SEQ, 256>>>(pS);

    // 4) out = P V   (per batch, NN)
    dim3 gO(DIM / BN, SEQ / BM, BATCH);
    gemm64<false, false><<<gO, 256>>>(pS, pV, nullptr, out,
                                      SEQ, DIM, SEQ,
                                      (long long)SEQ * SEQ, (long long)SEQ * DIM,
                                      (long long)SEQ * DIM, 1.0f);
}

// round 3
// speedup vs baseline: 3.1770x; 3.1770x over previous
#include <cuda_runtime.h>
#include <cuda_bf16.h>
#include <cstdint>
#include <math.h>

// ===========================================================================
// out = softmax((xWq+bq)(xWk+bk)^T / 32) (xWv+bv);  B=4, S=2048, D=H=1024
// All GEMMs via legacy mma.sync tf32 (base PTX, works at target sm_103).
// fp32 operands everywhere; in-register cvt.rna.tf32. No split arrays.
// ===========================================================================

#define BATCH 4
#define SEQ   2048
#define DIM   1024

// scratch (__device__ globals; no allocations allowed)
__device__ float g_Q[BATCH * SEQ * DIM];
__device__ float g_K[BATCH * SEQ * DIM];
__device__ float g_V[BATCH * SEQ * DIM];
__device__ float g_S[BATCH * SEQ * SEQ];

// ---------------- helpers ---------------------------------------------------
__device__ __forceinline__ uint32_t smem_u32(const void* p) {
    uint32_t a;
    asm("{ .reg .u64 t; cvta.to.shared.u64 t, %1; cvt.u32.u64 %0, t; }"
        : "=r"(a) : "l"(p));
    return a;
}
__device__ __forceinline__ void cp16(uint32_t saddr, const void* g) {
    asm volatile("cp.async.cg.shared.global [%0], [%1], 16;" :: "r"(saddr), "l"(g));
}
__device__ __forceinline__ uint32_t cvt_tf32(float x) {
    uint32_t r;
    asm("cvt.rna.tf32.f32 %0, %1;" : "=r"(r) : "f"(x));
    return r;
}
__device__ __forceinline__ void mma_tf32(float* c, const uint32_t* a, const uint32_t* b) {
    asm volatile(
        "mma.sync.aligned.m16n8k8.row.col.f32.tf32.tf32.f32 "
        "{%0,%1,%2,%3}, {%4,%5,%6,%7}, {%8,%9}, {%0,%1,%2,%3};"
        : "+f"(c[0]), "+f"(c[1]), "+f"(c[2]), "+f"(c[3])
        : "r"(a[0]), "r"(a[1]), "r"(a[2]), "r"(a[3]), "r"(b[0]), "r"(b[1]));
}

// ===========================================================================
// GEMM: C[M,N] = op(A[M,K] x B) (+bias | *alpha)
//   TRANSB=false: B is [K,N] row-major (ldb=N)
//   TRANSB=true : B is [N,K] row-major (ldb=K)  => C = A B^T
// lda=K, ldc=N at all call sites. M,N mult of 128; K mult of 32.
// Tile 128x128xBK32, 256 threads (8 warps as 2(m)x4(n), each 64x32),
// 3-stage cp.async pipeline.
// MODE: 0 = +bias, 1 = *alpha, 2 = plain
// ===========================================================================
#define TM 128
#define TN 128
#define KB 32
#define A_PITCH   36     // floats; bank-conflict-free fragment loads
#define BT_PITCH  36
#define BN_PITCH  132

#define ASTRIDE   (TM * A_PITCH)                     // floats per A stage (4608)
#define BSTRIDE_T (TN * BT_PITCH)                    // 4608
#define BSTRIDE_N (KB * BN_PITCH)                    // 4224
#define SMEM_T    (3 * (ASTRIDE + BSTRIDE_T) * 4)    // 110592 B
#define SMEM_N    (3 * (ASTRIDE + BSTRIDE_N) * 4)    // 105984 B

template <bool TRANSB, int MODE>
__global__ __launch_bounds__(256, 2)
void gemm_tf32(const float* __restrict__ A, const float* __restrict__ B,
               const float* __restrict__ bias, float* __restrict__ C,
               int M, int N, int K,
               long long sA, long long sB, long long sC, float alpha)
{
    extern __shared__ float sm[];
    const int tid  = threadIdx.x;
    const int wid  = tid >> 5;
    const int lane = tid & 31;
    const int gq = lane >> 2;      // groupID (0..7)
    const int tq = lane & 3;       // threadID_in_group (0..3)

    A += (long long)blockIdx.z * sA;
    B += (long long)blockIdx.z * sB;
    C += (long long)blockIdx.z * sC;
    const int m0 = blockIdx.y * TM;
    const int n0 = blockIdx.x * TN;
    const int wm = (wid >> 2) * 64;    // warp m offset (0/64)
    const int wn = (wid & 3) * 32;     // warp n offset (0/32/64/96)

    constexpr int BSTRIDE = TRANSB ? BSTRIDE_T : BSTRIDE_N;
    float* As = sm;                    // [3][ASTRIDE]
    float* Bs = sm + 3 * ASTRIDE;      // [3][BSTRIDE]

    auto loadA = [&](int k0, int s) {
        float* dst = As + s * ASTRIDE;
        const float* src = A + (long long)m0 * K + k0;
#pragma unroll
        for (int j = 0; j < 4; j++) {
            int idx = j * 256 + tid;
            int r = idx >> 3, ch = idx & 7;                    // 128 rows x 8 chunks
            cp16(smem_u32(dst + r * A_PITCH + ch * 4),
                 src + (long long)r * K + ch * 4);
        }
    };
    auto loadB = [&](int k0, int s) {
        float* dst = Bs + s * BSTRIDE;
        if (TRANSB) {
            const float* src = B + (long long)n0 * K + k0;
#pragma unroll
            for (int j = 0; j < 4; j++) {
                int idx = j * 256 + tid;
                int r = idx >> 3, ch = idx & 7;                // 128 n-rows x 8 chunks
                cp16(smem_u32(dst + r * BT_PITCH + ch * 4),
                     src + (long long)r * K + ch * 4);
            }
        } else {
            const float* src = B + (long long)k0 * N + n0;
#pragma unroll
            for (int j = 0; j < 4; j++) {
                int idx = j * 256 + tid;
                int r = idx >> 5, ch = idx & 31;               // 32 k-rows x 32 chunks
                cp16(smem_u32(dst + r * BN_PITCH + ch * 4),
                     src + (long long)r * N + ch * 4);
            }
        }
    };

    float acc[4][4][4] = {};    // [mtile][ntile][c0..c3]

    const int nIter = K / KB;
    loadA(0, 0); loadB(0, 0);
    asm volatile("cp.async.commit_group;" ::: "memory");
    loadA(KB, 1); loadB(KB, 1);
    asm volatile("cp.async.commit_group;" ::: "memory");

    for (int it = 0; it < nIter; it++) {
        asm volatile("cp.async.wait_group 1;" ::: "memory");
        __syncthreads();

        if (it + 2 < nIter) {
            loadA((it + 2) * KB, (it + 2) % 3);
            loadB((it + 2) * KB, (it + 2) % 3);
        }
        asm volatile("cp.async.commit_group;" ::: "memory");

        const float* a_s = As + (it % 3) * ASTRIDE;
        const float* b_s = Bs + (it % 3) * BSTRIDE;

#pragma unroll
        for (int kk = 0; kk < 4; kk++) {
            const int k = kk * 8;
            uint32_t af[4][4];
#pragma unroll
            for (int i = 0; i < 4; i++) {
                const float* ap = a_s + (wm + i * 16 + gq) * A_PITCH + k + tq;
                af[i][0] = cvt_tf32(ap[0]);
                af[i][1] = cvt_tf32(ap[8 * A_PITCH]);
                af[i][2] = cvt_tf32(ap[4]);
                af[i][3] = cvt_tf32(ap[8 * A_PITCH + 4]);
            }
            uint32_t bf[4][2];
#pragma unroll
            for (int j = 0; j < 4; j++) {
                if (TRANSB) {
                    const float* bp = b_s + (wn + j * 8 + gq) * BT_PITCH + k + tq;
                    bf[j][0] = cvt_tf32(bp[0]);
                    bf[j][1] = cvt_tf32(bp[4]);
                } else {
                    const float* bp = b_s + (k + tq) * BN_PITCH + wn + j * 8 + gq;
                    bf[j][0] = cvt_tf32(bp[0]);
                    bf[j][1] = cvt_tf32(bp[4 * BN_PITCH]);
                }
            }
#pragma unroll
            for (int i = 0; i < 4; i++)
#pragma unroll
                for (int j = 0; j < 4; j++)
                    mma_tf32(acc[i][j], af[i], bf[j]);
        }
        // no trailing sync needed: next iteration's wait+syncthreads protects
        // stage reuse (stage (it+2)%3 was consumed in iteration it-1).
        __syncthreads();
    }

    // epilogue
#pragma unroll
    for (int i = 0; i < 4; i++) {
#pragma unroll
        for (int j = 0; j < 4; j++) {
            const int r = m0 + wm + i * 16 + gq;
            const int c = n0 + wn + j * 8 + 2 * tq;
            float2 v0 = make_float2(acc[i][j][0], acc[i][j][1]);
            float2 v1 = make_float2(acc[i][j][2], acc[i][j][3]);
            if (MODE == 0) {
                float2 bz = *reinterpret_cast<const float2*>(bias + c);
                v0.x += bz.x; v0.y += bz.y;
                v1.x += bz.x; v1.y += bz.y;
            }
            if (MODE == 1) {
                v0.x *= alpha; v0.y *= alpha;
                v1.x *= alpha; v1.y *= alpha;
            }
            *reinterpret_cast<float2*>(C + (long long)r * N + c) = v0;
            *reinterpret_cast<float2*>(C + (long long)(r + 8) * N + c) = v1;
        }
    }
}

// ---------------------------------------------------------------------------
// Row softmax over rows of length SEQ (2048), in place.
// ---------------------------------------------------------------------------
__global__ __launch_bounds__(256)
void softmax_rows(float* __restrict__ S)
{
    float* row = S + (long long)blockIdx.x * SEQ;
    __shared__ float red[256];
    const int t = threadIdx.x;

    float v[8];
    float mx = -INFINITY;
#pragma unroll
    for (int i = 0; i < 8; i++) {
        v[i] = row[t + i * 256];
        mx = fmaxf(mx, v[i]);
    }
    red[t] = mx;
    __syncthreads();
#pragma unroll
    for (int s = 128; s > 0; s >>= 1) {
        if (t < s) red[t] = fmaxf(red[t], red[t + s]);
        __syncthreads();
    }
    mx = red[0];
    __syncthreads();

    float sum = 0.f;
#pragma unroll
    for (int i = 0; i < 8; i++) {
        v[i] = __expf(v[i] - mx);
        sum += v[i];
    }
    red[t] = sum;
    __syncthreads();
#pragma unroll
    for (int s = 128; s > 0; s >>= 1) {
        if (t < s) red[t] += red[t + s];
        __syncthreads();
    }
    float inv = 1.0f / red[0];
#pragma unroll
    for (int i = 0; i < 8; i++)
        row[t + i * 256] = v[i] * inv;
}

// ---------------------------------------------------------------------------
// launch;  inputs: x, Wq, bq, Wk, bk, Wv, bv
// ---------------------------------------------------------------------------
extern "C" void kernel_launch(void* const* d_in, const int* in_sizes, int n_in,
                              void* d_out, int out_size)
{
    const float* x  = (const float*)d_in[0];
    const float* Wq = (const float*)d_in[1];
    const float* bq = (const float*)d_in[2];
    const float* Wk = (const float*)d_in[3];
    const float* bk = (const float*)d_in[4];
    const float* Wv = (const float*)d_in[5];
    const float* bv = (const float*)d_in[6];
    float* out = (float*)d_out;

    static float *pQ = nullptr, *pK = nullptr, *pV = nullptr, *pS = nullptr;
    if (!pQ) {
        cudaGetSymbolAddress((void**)&pQ, g_Q);
        cudaGetSymbolAddress((void**)&pK, g_K);
        cudaGetSymbolAddress((void**)&pV, g_V);
        cudaGetSymbolAddress((void**)&pS, g_S);
        cudaFuncSetAttribute(gemm_tf32<false, 0>, cudaFuncAttributeMaxDynamicSharedMemorySize, SMEM_N);
        cudaFuncSetAttribute(gemm_tf32<true, 1>,  cudaFuncAttributeMaxDynamicSharedMemorySize, SMEM_T);
        cudaFuncSetAttribute(gemm_tf32<false, 2>, cudaFuncAttributeMaxDynamicSharedMemorySize, SMEM_N);
    }

    const int M = BATCH * SEQ;          // 8192
    const float scale = 0.03125f;       // 1/sqrt(1024)

    // 1) QKV projections: [8192,1024] x [1024,1024] + bias
    dim3 gP(DIM / TN, M / TM, 1);
    gemm_tf32<false, 0><<<gP, 256, SMEM_N>>>(x, Wq, bq, pQ, M, DIM, DIM, 0, 0, 0, 1.f);
    gemm_tf32<false, 0><<<gP, 256, SMEM_N>>>(x, Wk, bk, pK, M, DIM, DIM, 0, 0, 0, 1.f);
    gemm_tf32<false, 0><<<gP, 256, SMEM_N>>>(x, Wv, bv, pV, M, DIM, DIM, 0, 0, 0, 1.f);

    // 2) scores = Q K^T * scale (per batch, NT)
    dim3 gS(SEQ / TN, SEQ / TM, BATCH);
    gemm_tf32<true, 1><<<gS, 256, SMEM_T>>>(pQ, pK, nullptr, pS,
                                            SEQ, SEQ, DIM,
                                            (long long)SEQ * DIM, (long long)SEQ * DIM,
                                            (long long)SEQ * SEQ, scale);

    // 3) softmax rows (in place)
    softmax_rows<<<BATCH * SEQ, 256>>>(pS);

    // 4) out = P V (per batch, NN)
    dim3 gO(DIM / TN, SEQ / TM, BATCH);
    gemm_tf32<false, 2><<<gO, 256, SMEM_N>>>(pS, pV, nullptr, out,
                                             SEQ, DIM, SEQ,
                                             (long long)SEQ * SEQ, (long long)SEQ * DIM,
                                             (long long)SEQ * DIM, 1.f);
}

// round 4
// speedup vs baseline: 3.3631x; 1.0586x over previous
#include <cuda_runtime.h>
#include <cuda_bf16.h>
#include <cstdint>
#include <math.h>

// ===========================================================================
// out = softmax((xWq+bq)(xWk+bk)^T / 32) (xWv+bv);  B=4, S=2048, D=H=1024
// All GEMMs via legacy mma.sync tf32 (base PTX, works at target sm_103).
// All operands pre-rounded to tf32 by producers => mainloop has ZERO cvt:
// raw f32 bits from SMEM are exact tf32 values (low 13 mantissa bits = 0).
// ===========================================================================

#define BATCH 4
#define SEQ   2048
#define DIM   1024

// scratch (__device__ globals; no allocations allowed)
__device__ float g_Q [BATCH * SEQ * DIM];
__device__ float g_K [BATCH * SEQ * DIM];
__device__ float g_V [BATCH * SEQ * DIM];
__device__ float g_S [BATCH * SEQ * SEQ];
__device__ float g_xr[BATCH * SEQ * DIM];     // x rounded to tf32
__device__ float g_Wr[3 * DIM * DIM];         // Wq|Wk|Wv rounded to tf32

// ---------------- helpers ---------------------------------------------------
__device__ __forceinline__ uint32_t smem_u32(const void* p) {
    uint32_t a;
    asm("{ .reg .u64 t; cvta.to.shared.u64 t, %1; cvt.u32.u64 %0, t; }"
        : "=r"(a) : "l"(p));
    return a;
}
__device__ __forceinline__ void cp16(uint32_t saddr, const void* g) {
    asm volatile("cp.async.cg.shared.global [%0], [%1], 16;" :: "r"(saddr), "l"(g));
}
__device__ __forceinline__ float round_tf32(float x) {
    uint32_t r;
    asm("cvt.rna.tf32.f32 %0, %1;" : "=r"(r) : "f"(x));
    return __uint_as_float(r);
}
__device__ __forceinline__ void mma_tf32(float* c, const uint32_t* a, const uint32_t* b) {
    asm volatile(
        "mma.sync.aligned.m16n8k8.row.col.f32.tf32.tf32.f32 "
        "{%0,%1,%2,%3}, {%4,%5,%6,%7}, {%8,%9}, {%0,%1,%2,%3};"
        : "+f"(c[0]), "+f"(c[1]), "+f"(c[2]), "+f"(c[3])
        : "r"(a[0]), "r"(a[1]), "r"(a[2]), "r"(a[3]), "r"(b[0]), "r"(b[1]));
}

// ===========================================================================
// GEMM: C[M,N] = op(A[M,K] x B)
//   TRANSB=false: B is [K,N] row-major (ldb=N)
//   TRANSB=true : B is [N,K] row-major (ldb=K)  => C = A B^T
// Tile 128x128xKB32, 256 threads (2(m)x4(n) warps, each 64x32), 3-stage
// cp.async pipeline. Operands must already be tf32-rounded.
// MODE: 1 = *alpha, 2 = plain, 3 = +bias then tf32-round
// ===========================================================================
#define TM 128
#define TN 128
#define KB 32
#define A_PITCH   36
#define BT_PITCH  36
#define BN_PITCH  132

#define ASTRIDE   (TM * A_PITCH)
#define BSTRIDE_T (TN * BT_PITCH)
#define BSTRIDE_N (KB * BN_PITCH)
#define SMEM_T    (3 * (ASTRIDE + BSTRIDE_T) * 4)    // 110592 B
#define SMEM_N    (3 * (ASTRIDE + BSTRIDE_N) * 4)    // 105984 B

template <bool TRANSB, int MODE>
__global__ __launch_bounds__(256, 2)
void gemm_tf32(const float* __restrict__ A, const float* __restrict__ B,
               const float* __restrict__ bias, float* __restrict__ C,
               int M, int N, int K,
               long long sA, long long sB, long long sC, float alpha)
{
    extern __shared__ float sm[];
    const int tid  = threadIdx.x;
    const int wid  = tid >> 5;
    const int lane = tid & 31;
    const int gq = lane >> 2;      // groupID (0..7)
    const int tq = lane & 3;       // threadID_in_group (0..3)

    A += (long long)blockIdx.z * sA;
    B += (long long)blockIdx.z * sB;
    C += (long long)blockIdx.z * sC;
    const int m0 = blockIdx.y * TM;
    const int n0 = blockIdx.x * TN;
    const int wm = (wid >> 2) * 64;
    const int wn = (wid & 3) * 32;

    constexpr int BSTRIDE = TRANSB ? BSTRIDE_T : BSTRIDE_N;
    float* As = sm;
    float* Bs = sm + 3 * ASTRIDE;

    auto loadA = [&](int k0, int s) {
        float* dst = As + s * ASTRIDE;
        const float* src = A + (long long)m0 * K + k0;
#pragma unroll
        for (int j = 0; j < 4; j++) {
            int idx = j * 256 + tid;
            int r = idx >> 3, ch = idx & 7;
            cp16(smem_u32(dst + r * A_PITCH + ch * 4),
                 src + (long long)r * K + ch * 4);
        }
    };
    auto loadB = [&](int k0, int s) {
        float* dst = Bs + s * BSTRIDE;
        if (TRANSB) {
            const float* src = B + (long long)n0 * K + k0;
#pragma unroll
            for (int j = 0; j < 4; j++) {
                int idx = j * 256 + tid;
                int r = idx >> 3, ch = idx & 7;
                cp16(smem_u32(dst + r * BT_PITCH + ch * 4),
                     src + (long long)r * K + ch * 4);
            }
        } else {
            const float* src = B + (long long)k0 * N + n0;
#pragma unroll
            for (int j = 0; j < 4; j++) {
                int idx = j * 256 + tid;
                int r = idx >> 5, ch = idx & 31;
                cp16(smem_u32(dst + r * BN_PITCH + ch * 4),
                     src + (long long)r * N + ch * 4);
            }
        }
    };

    float acc[4][4][4] = {};

    const int nIter = K / KB;
    loadA(0, 0); loadB(0, 0);
    asm volatile("cp.async.commit_group;" ::: "memory");
    loadA(KB, 1); loadB(KB, 1);
    asm volatile("cp.async.commit_group;" ::: "memory");

    for (int it = 0; it < nIter; it++) {
        asm volatile("cp.async.wait_group 1;" ::: "memory");
        __syncthreads();

        if (it + 2 < nIter) {
            loadA((it + 2) * KB, (it + 2) % 3);
            loadB((it + 2) * KB, (it + 2) % 3);
        }
        asm volatile("cp.async.commit_group;" ::: "memory");

        const uint32_t* a_s = reinterpret_cast<const uint32_t*>(As + (it % 3) * ASTRIDE);
        const uint32_t* b_s = reinterpret_cast<const uint32_t*>(Bs + (it % 3) * BSTRIDE);

#pragma unroll
        for (int kk = 0; kk < 4; kk++) {
            const int k = kk * 8;
            uint32_t af[4][4];
#pragma unroll
            for (int i = 0; i < 4; i++) {
                const uint32_t* ap = a_s + (wm + i * 16 + gq) * A_PITCH + k + tq;
                af[i][0] = ap[0];
                af[i][1] = ap[8 * A_PITCH];
                af[i][2] = ap[4];
                af[i][3] = ap[8 * A_PITCH + 4];
            }
            uint32_t bf[4][2];
#pragma unroll
            for (int j = 0; j < 4; j++) {
                if (TRANSB) {
                    const uint32_t* bp = b_s + (wn + j * 8 + gq) * BT_PITCH + k + tq;
                    bf[j][0] = bp[0];
                    bf[j][1] = bp[4];
                } else {
                    const uint32_t* bp = b_s + (k + tq) * BN_PITCH + wn + j * 8 + gq;
                    bf[j][0] = bp[0];
                    bf[j][1] = bp[4 * BN_PITCH];
                }
            }
#pragma unroll
            for (int i = 0; i < 4; i++)
#pragma unroll
                for (int j = 0; j < 4; j++)
                    mma_tf32(acc[i][j], af[i], bf[j]);
        }
        __syncthreads();
    }

    // epilogue
#pragma unroll
    for (int i = 0; i < 4; i++) {
#pragma unroll
        for (int j = 0; j < 4; j++) {
            const int r = m0 + wm + i * 16 + gq;
            const int c = n0 + wn + j * 8 + 2 * tq;
            float2 v0 = make_float2(acc[i][j][0], acc[i][j][1]);
            float2 v1 = make_float2(acc[i][j][2], acc[i][j][3]);
            if (MODE == 3) {
                float2 bz = *reinterpret_cast<const float2*>(bias + c);
                v0.x = round_tf32(v0.x + bz.x);
                v0.y = round_tf32(v0.y + bz.y);
                v1.x = round_tf32(v1.x + bz.x);
                v1.y = round_tf32(v1.y + bz.y);
            }
            if (MODE == 1) {
                v0.x *= alpha; v0.y *= alpha;
                v1.x *= alpha; v1.y *= alpha;
            }
            *reinterpret_cast<float2*>(C + (long long)r * N + c) = v0;
            *reinterpret_cast<float2*>(C + (long long)(r + 8) * N + c) = v1;
        }
    }
}

// ---------------------------------------------------------------------------
// Elementwise tf32 rounding: dst = round_tf32(src), n multiple of 1024 floats
// ---------------------------------------------------------------------------
__global__ __launch_bounds__(256)
void round_pass(const float* __restrict__ src, float* __restrict__ dst)
{
    int idx = blockIdx.x * 256 + threadIdx.x;
    float4 v = reinterpret_cast<const float4*>(src)[idx];
    v.x = round_tf32(v.x); v.y = round_tf32(v.y);
    v.z = round_tf32(v.z); v.w = round_tf32(v.w);
    reinterpret_cast<float4*>(dst)[idx] = v;
}

// ---------------------------------------------------------------------------
// Row softmax over rows of length SEQ (2048), in place; output tf32-rounded.
// ---------------------------------------------------------------------------
__global__ __launch_bounds__(256)
void softmax_rows(float* __restrict__ S)
{
    float* row = S + (long long)blockIdx.x * SEQ;
    __shared__ float red[256];
    const int t = threadIdx.x;

    float v[8];
    float mx = -INFINITY;
#pragma unroll
    for (int i = 0; i < 8; i++) {
        v[i] = row[t + i * 256];
        mx = fmaxf(mx, v[i]);
    }
    red[t] = mx;
    __syncthreads();
#pragma unroll
    for (int s = 128; s > 0; s >>= 1) {
        if (t < s) red[t] = fmaxf(red[t], red[t + s]);
        __syncthreads();
    }
    mx = red[0];
    __syncthreads();

    float sum = 0.f;
#pragma unroll
    for (int i = 0; i < 8; i++) {
        v[i] = __expf(v[i] - mx);
        sum += v[i];
    }
    red[t] = sum;
    __syncthreads();
#pragma unroll
    for (int s = 128; s > 0; s >>= 1) {
        if (t < s) red[t] += red[t + s];
        __syncthreads();
    }
    float inv = 1.0f / red[0];
#pragma unroll
    for (int i = 0; i < 8; i++)
        row[t + i * 256] = round_tf32(v[i] * inv);
}

// ---------------------------------------------------------------------------
// launch;  inputs: x, Wq, bq, Wk, bk, Wv, bv
// ---------------------------------------------------------------------------
extern "C" void kernel_launch(void* const* d_in, const int* in_sizes, int n_in,
                              void* d_out, int out_size)
{
    const float* x  = (const float*)d_in[0];
    const float* Wq = (const float*)d_in[1];
    const float* bq = (const float*)d_in[2];
    const float* Wk = (const float*)d_in[3];
    const float* bk = (const float*)d_in[4];
    const float* Wv = (const float*)d_in[5];
    const float* bv = (const float*)d_in[6];
    float* out = (float*)d_out;

    static float *pQ = nullptr, *pK = nullptr, *pV = nullptr, *pS = nullptr,
                 *pxr = nullptr, *pWr = nullptr;
    if (!pQ) {
        cudaGetSymbolAddress((void**)&pQ,  g_Q);
        cudaGetSymbolAddress((void**)&pK,  g_K);
        cudaGetSymbolAddress((void**)&pV,  g_V);
        cudaGetSymbolAddress((void**)&pS,  g_S);
        cudaGetSymbolAddress((void**)&pxr, g_xr);
        cudaGetSymbolAddress((void**)&pWr, g_Wr);
        cudaFuncSetAttribute(gemm_tf32<false, 3>, cudaFuncAttributeMaxDynamicSharedMemorySize, SMEM_N);
        cudaFuncSetAttribute(gemm_tf32<true, 1>,  cudaFuncAttributeMaxDynamicSharedMemorySize, SMEM_T);
        cudaFuncSetAttribute(gemm_tf32<false, 2>, cudaFuncAttributeMaxDynamicSharedMemorySize, SMEM_N);
    }

    const int M = BATCH * SEQ;          // 8192
    const float scale = 0.03125f;       // 1/sqrt(1024)

    // 0) pre-round inputs to tf32 (x: 8M floats; W: 3x1M floats)
    round_pass<<<M * DIM / 1024, 256>>>(x, pxr);
    round_pass<<<DIM * DIM / 1024, 256>>>(Wq, pWr);
    round_pass<<<DIM * DIM / 1024, 256>>>(Wk, pWr + DIM * DIM);
    round_pass<<<DIM * DIM / 1024, 256>>>(Wv, pWr + 2 * DIM * DIM);

    // 1) QKV projections (epilogue rounds outputs to tf32)
    dim3 gP(DIM / TN, M / TM, 1);
    gemm_tf32<false, 3><<<gP, 256, SMEM_N>>>(pxr, pWr,               bq, pQ, M, DIM, DIM, 0, 0, 0, 1.f);
    gemm_tf32<false, 3><<<gP, 256, SMEM_N>>>(pxr, pWr + DIM * DIM,   bk, pK, M, DIM, DIM, 0, 0, 0, 1.f);
    gemm_tf32<false, 3><<<gP, 256, SMEM_N>>>(pxr, pWr + 2 * DIM * DIM, bv, pV, M, DIM, DIM, 0, 0, 0, 1.f);

    // 2) scores = Q K^T * scale (per batch, NT)
    dim3 gS(SEQ / TN, SEQ / TM, BATCH);
    gemm_tf32<true, 1><<<gS, 256, SMEM_T>>>(pQ, pK, nullptr, pS,
                                            SEQ, SEQ, DIM,
                                            (long long)SEQ * DIM, (long long)SEQ * DIM,
                                            (long long)SEQ * SEQ, scale);

    // 3) softmax rows (in place, output tf32-rounded)
    softmax_rows<<<BATCH * SEQ, 256>>>(pS);

    // 4) out = P V (per batch, NN)
    dim3 gO(DIM / TN, SEQ / TM, BATCH);
    gemm_tf32<false, 2><<<gO, 256, SMEM_N>>>(pS, pV, nullptr, out,
                                             SEQ, DIM, SEQ,
                                             (long long)SEQ * SEQ, (long long)SEQ * DIM,
                                             (long long)SEQ * DIM, 1.f);
}

// round 5
// speedup vs baseline: 3.8553x; 1.1463x over previous
#include <cuda_runtime.h>
#include <cuda_bf16.h>
#include <cstdint>
#include <math.h>

// ===========================================================================
// out = softmax((xWq+bq)(xWk+bk)^T / 32) (xWv+bv);  B=4, S=2048, D=H=1024
// All GEMMs via mma.sync tf32. Operands pre-rounded to tf32 by producers.
// Fragment loads use a k-position remap (slots (tq,tq+4) <- positions
// (2tq,2tq+1), identically on A and B sides) enabling LDS.64, with XOR-
// swizzled 128B-row SMEM tiles (conflict-free, cp.async-compatible).
// ===========================================================================

#define BATCH 4
#define SEQ   2048
#define DIM   1024

__device__ float g_Q [BATCH * SEQ * DIM];
__device__ float g_K [BATCH * SEQ * DIM];
__device__ float g_V [BATCH * SEQ * DIM];
__device__ float g_S [BATCH * SEQ * SEQ];
__device__ float g_xr[BATCH * SEQ * DIM];
__device__ float g_Wr[3 * DIM * DIM];

// ---------------- helpers ---------------------------------------------------
__device__ __forceinline__ uint32_t smem_u32(const void* p) {
    uint32_t a;
    asm("{ .reg .u64 t; cvta.to.shared.u64 t, %1; cvt.u32.u64 %0, t; }"
        : "=r"(a) : "l"(p));
    return a;
}
__device__ __forceinline__ void cp16(uint32_t saddr, const void* g) {
    asm volatile("cp.async.cg.shared.global [%0], [%1], 16;" :: "r"(saddr), "l"(g));
}
__device__ __forceinline__ float round_tf32(float x) {
    uint32_t r;
    asm("cvt.rna.tf32.f32 %0, %1;" : "=r"(r) : "f"(x));
    return __uint_as_float(r);
}
__device__ __forceinline__ void mma_tf32(float* c, const uint32_t* a, const uint32_t* b) {
    asm volatile(
        "mma.sync.aligned.m16n8k8.row.col.f32.tf32.tf32.f32 "
        "{%0,%1,%2,%3}, {%4,%5,%6,%7}, {%8,%9}, {%0,%1,%2,%3};"
        : "+f"(c[0]), "+f"(c[1]), "+f"(c[2]), "+f"(c[3])
        : "r"(a[0]), "r"(a[1]), "r"(a[2]), "r"(a[3]), "r"(b[0]), "r"(b[1]));
}

// ===========================================================================
// GEMM 128x128xKB32, 256 thr (2x4 warps of 64x32), 3-stage cp.async.
//   TRANSB=false: B [K,N] row-major;  TRANSB=true: B [N,K] (C = A B^T)
// A tile & B-NT tile: 128 rows x 128B, swizzle c64' = c64 ^ ((row&3)<<2).
// B-NN tile: [32][132] padded floats.
// MODE: 1 = *alpha, 2 = plain, 3 = +bias then tf32-round
// ===========================================================================
#define TM 128
#define TN 128
#define KB 32
#define BN_PITCH  132

#define ASTRIDE   (TM * 32)                 // 4096 floats (swizzled 128B rows)
#define BSTRIDE_T (TN * 32)                 // 4096
#define BSTRIDE_N (KB * BN_PITCH)           // 4224
#define SMEM_T    (3 * (ASTRIDE + BSTRIDE_T) * 4)   //  98304 B
#define SMEM_N    (3 * (ASTRIDE + BSTRIDE_N) * 4)   //  99840 B

template <bool TRANSB, int MODE>
__global__ __launch_bounds__(256, 2)
void gemm_tf32(const float* __restrict__ A, const float* __restrict__ B,
               const float* __restrict__ bias, float* __restrict__ C,
               int M, int N, int K,
               long long sA, long long sB, long long sC, float alpha)
{
    extern __shared__ float sm[];
    const int tid  = threadIdx.x;
    const int wid  = tid >> 5;
    const int lane = tid & 31;
    const int gq = lane >> 2;      // groupID (0..7)
    const int tq = lane & 3;       // threadID_in_group (0..3)

    A += (long long)blockIdx.z * sA;
    B += (long long)blockIdx.z * sB;
    C += (long long)blockIdx.z * sC;
    const int m0 = blockIdx.y * TM;
    const int n0 = blockIdx.x * TN;
    const int wm = (wid >> 2) * 64;
    const int wn = (wid & 3) * 32;

    constexpr int BSTRIDE = TRANSB ? BSTRIDE_T : BSTRIDE_N;
    float* As = sm;
    float* Bs = sm + 3 * ASTRIDE;

    // swizzled-tile writer mapping (A and B-NT): thread -> (row, 16B chunk)
    // float offset = row*32 + ((2*ch) ^ ((row&3)<<2)) * 2
    auto loadA = [&](int k0, int s) {
        float* dst = As + s * ASTRIDE;
        const float* src = A + (long long)m0 * K + k0;
#pragma unroll
        for (int j = 0; j < 4; j++) {
            int idx = j * 256 + tid;
            int r = idx >> 3, ch = idx & 7;
            int off = r * 32 + (((2 * ch) ^ ((r & 3) << 2)) << 1);
            cp16(smem_u32(dst + off), src + (long long)r * K + ch * 4);
        }
    };
    auto loadB = [&](int k0, int s) {
        float* dst = Bs + s * BSTRIDE;
        if (TRANSB) {
            const float* src = B + (long long)n0 * K + k0;
#pragma unroll
            for (int j = 0; j < 4; j++) {
                int idx = j * 256 + tid;
                int r = idx >> 3, ch = idx & 7;
                int off = r * 32 + (((2 * ch) ^ ((r & 3) << 2)) << 1);
                cp16(smem_u32(dst + off), src + (long long)r * K + ch * 4);
            }
        } else {
            const float* src = B + (long long)k0 * N + n0;
#pragma unroll
            for (int j = 0; j < 4; j++) {
                int idx = j * 256 + tid;
                int r = idx >> 5, ch = idx & 31;
                cp16(smem_u32(dst + r * BN_PITCH + ch * 4),
                     src + (long long)r * N + ch * 4);
            }
        }
    };

    float acc[4][4][4] = {};

    const int nIter = K / KB;
    loadA(0, 0); loadB(0, 0);
    asm volatile("cp.async.commit_group;" ::: "memory");
    loadA(KB, 1); loadB(KB, 1);
    asm volatile("cp.async.commit_group;" ::: "memory");

    const int axk = (gq & 3) << 2;                 // swizzle key for this lane

    for (int it = 0; it < nIter; it++) {
        asm volatile("cp.async.wait_group 1;" ::: "memory");
        __syncthreads();

        if (it + 2 < nIter) {
            loadA((it + 2) * KB, (it + 2) % 3);
            loadB((it + 2) * KB, (it + 2) % 3);
        }
        asm volatile("cp.async.commit_group;" ::: "memory");

        const float* a_s = As + (it % 3) * ASTRIDE;
        const float* b_s = Bs + (it % 3) * BSTRIDE;

#pragma unroll
        for (int kk = 0; kk < 4; kk++) {
            const int cA = (((kk << 2) + tq) ^ axk) << 1;   // float offset in row
            uint32_t af[4][4];
#pragma unroll
            for (int i = 0; i < 4; i++) {
                const float* ap = a_s + (wm + i * 16 + gq) * 32 + cA;
                uint2 u0 = *reinterpret_cast<const uint2*>(ap);
                uint2 u1 = *reinterpret_cast<const uint2*>(ap + 8 * 32);
                af[i][0] = u0.x; af[i][1] = u1.x;           // slots k=tq
                af[i][2] = u0.y; af[i][3] = u1.y;           // slots k=tq+4
            }
            uint32_t bf[4][2];
#pragma unroll
            for (int j = 0; j < 4; j++) {
                if (TRANSB) {
                    const float* bp = b_s + (wn + j * 8 + gq) * 32 + cA;
                    uint2 v = *reinterpret_cast<const uint2*>(bp);
                    bf[j][0] = v.x; bf[j][1] = v.y;
                } else {
                    const float* bp = b_s + (8 * kk + 2 * tq) * BN_PITCH + wn + j * 8 + gq;
                    bf[j][0] = __float_as_uint(bp[0]);
                    bf[j][1] = __float_as_uint(bp[BN_PITCH]);
                }
            }
#pragma unroll
            for (int i = 0; i < 4; i++)
#pragma unroll
                for (int j = 0; j < 4; j++)
                    mma_tf32(acc[i][j], af[i], bf[j]);
        }
        // top-of-loop barrier (after wait_group) is sufficient ordering for
        // stage reuse: no trailing __syncthreads needed.
    }

    // epilogue
#pragma unroll
    for (int i = 0; i < 4; i++) {
#pragma unroll
        for (int j = 0; j < 4; j++) {
            const int r = m0 + wm + i * 16 + gq;
            const int c = n0 + wn + j * 8 + 2 * tq;
            float2 v0 = make_float2(acc[i][j][0], acc[i][j][1]);
            float2 v1 = make_float2(acc[i][j][2], acc[i][j][3]);
            if (MODE == 3) {
                float2 bz = *reinterpret_cast<const float2*>(bias + c);
                v0.x = round_tf32(v0.x + bz.x);
                v0.y = round_tf32(v0.y + bz.y);
                v1.x = round_tf32(v1.x + bz.x);
                v1.y = round_tf32(v1.y + bz.y);
            }
            if (MODE == 1) {
                v0.x *= alpha; v0.y *= alpha;
                v1.x *= alpha; v1.y *= alpha;
            }
            *reinterpret_cast<float2*>(C + (long long)r * N + c) = v0;
            *reinterpret_cast<float2*>(C + (long long)(r + 8) * N + c) = v1;
        }
    }
}

// ---------------------------------------------------------------------------
__global__ __launch_bounds__(256)
void round_pass(const float* __restrict__ src, float* __restrict__ dst)
{
    int idx = blockIdx.x * 256 + threadIdx.x;
    float4 v = reinterpret_cast<const float4*>(src)[idx];
    v.x = round_tf32(v.x); v.y = round_tf32(v.y);
    v.z = round_tf32(v.z); v.w = round_tf32(v.w);
    reinterpret_cast<float4*>(dst)[idx] = v;
}

// ---------------------------------------------------------------------------
__global__ __launch_bounds__(256)
void softmax_rows(float* __restrict__ S)
{
    float* row = S + (long long)blockIdx.x * SEQ;
    __shared__ float red[256];
    const int t = threadIdx.x;

    float v[8];
    float mx = -INFINITY;
#pragma unroll
    for (int i = 0; i < 8; i++) {
        v[i] = row[t + i * 256];
        mx = fmaxf(mx, v[i]);
    }
    red[t] = mx;
    __syncthreads();
#pragma unroll
    for (int s = 128; s > 0; s >>= 1) {
        if (t < s) red[t] = fmaxf(red[t], red[t + s]);
        __syncthreads();
    }
    mx = red[0];
    __syncthreads();

    float sum = 0.f;
#pragma unroll
    for (int i = 0; i < 8; i++) {
        v[i] = __expf(v[i] - mx);
        sum += v[i];
    }
    red[t] = sum;
    __syncthreads();
#pragma unroll
    for (int s = 128; s > 0; s >>= 1) {
        if (t < s) red[t] += red[t + s];
        __syncthreads();
    }
    float inv = 1.0f / red[0];
#pragma unroll
    for (int i = 0; i < 8; i++)
        row[t + i * 256] = round_tf32(v[i] * inv);
}

// ---------------------------------------------------------------------------
extern "C" void kernel_launch(void* const* d_in, const int* in_sizes, int n_in,
                              void* d_out, int out_size)
{
    const float* x  = (const float*)d_in[0];
    const float* Wq = (const float*)d_in[1];
    const float* bq = (const float*)d_in[2];
    const float* Wk = (const float*)d_in[3];
    const float* bk = (const float*)d_in[4];
    const float* Wv = (const float*)d_in[5];
    const float* bv = (const float*)d_in[6];
    float* out = (float*)d_out;

    static float *pQ = nullptr, *pK = nullptr, *pV = nullptr, *pS = nullptr,
                 *pxr = nullptr, *pWr = nullptr;
    if (!pQ) {
        cudaGetSymbolAddress((void**)&pQ,  g_Q);
        cudaGetSymbolAddress((void**)&pK,  g_K);
        cudaGetSymbolAddress((void**)&pV,  g_V);
        cudaGetSymbolAddress((void**)&pS,  g_S);
        cudaGetSymbolAddress((void**)&pxr, g_xr);
        cudaGetSymbolAddress((void**)&pWr, g_Wr);
        cudaFuncSetAttribute(gemm_tf32<false, 3>, cudaFuncAttributeMaxDynamicSharedMemorySize, SMEM_N);
        cudaFuncSetAttribute(gemm_tf32<true, 1>,  cudaFuncAttributeMaxDynamicSharedMemorySize, SMEM_T);
        cudaFuncSetAttribute(gemm_tf32<false, 2>, cudaFuncAttributeMaxDynamicSharedMemorySize, SMEM_N);
    }

    const int M = BATCH * SEQ;          // 8192
    const float scale = 0.03125f;       // 1/sqrt(1024)

    // 0) pre-round inputs to tf32
    round_pass<<<M * DIM / 1024, 256>>>(x, pxr);
    round_pass<<<DIM * DIM / 1024, 256>>>(Wq, pWr);
    round_pass<<<DIM * DIM / 1024, 256>>>(Wk, pWr + DIM * DIM);
    round_pass<<<DIM * DIM / 1024, 256>>>(Wv, pWr + 2 * DIM * DIM);

    // 1) QKV projections (epilogue rounds outputs to tf32)
    dim3 gP(DIM / TN, M / TM, 1);
    gemm_tf32<false, 3><<<gP, 256, SMEM_N>>>(pxr, pWr,                 bq, pQ, M, DIM, DIM, 0, 0, 0, 1.f);
    gemm_tf32<false, 3><<<gP, 256, SMEM_N>>>(pxr, pWr + DIM * DIM,     bk, pK, M, DIM, DIM, 0, 0, 0, 1.f);
    gemm_tf32<false, 3><<<gP, 256, SMEM_N>>>(pxr, pWr + 2 * DIM * DIM, bv, pV, M, DIM, DIM, 0, 0, 0, 1.f);

    // 2) scores = Q K^T * scale (per batch, NT)
    dim3 gS(SEQ / TN, SEQ / TM, BATCH);
    gemm_tf32<true, 1><<<gS, 256, SMEM_T>>>(pQ, pK, nullptr, pS,
                                            SEQ, SEQ, DIM,
                                            (long long)SEQ * DIM, (long long)SEQ * DIM,
                                            (long long)SEQ * SEQ, scale);

    // 3) softmax rows (in place, output tf32-rounded)
    softmax_rows<<<BATCH * SEQ, 256>>>(pS);

    // 4) out = P V (per batch, NN)
    dim3 gO(DIM / TN, SEQ / TM, BATCH);
    gemm_tf32<false, 2><<<gO, 256, SMEM_N>>>(pS, pV, nullptr, out,
                                             SEQ, DIM, SEQ,
                                             (long long)SEQ * SEQ, (long long)SEQ * DIM,
                                             (long long)SEQ * DIM, 1.f);
}